// round 1
// baseline (speedup 1.0000x reference)
#include <cuda_runtime.h>
#include <math.h>

#define E_EDGES 800000
#define NN 50000
#define D_N 64
#define HID 128
#define D_OUT 64
#define KX 192     // 2*D_N + D_E
#define BE 64      // edges per block

typedef unsigned long long ull;

__device__ int g_idx64;                       // 1 if src/dst are int64, 0 if int32
__device__ float g_agg[(size_t)NN * D_OUT];   // scatter-sum scratch

// packed fp32x2 FMA (d = a*b + d), pack/unpack helpers
#define FMA2(d, a, b) asm("fma.rn.f32x2 %0, %1, %2, %0;" : "+l"(d) : "l"(a), "l"(b))
#define PACK2(d, f)   asm("mov.b64 %0, {%1, %1};" : "=l"(d) : "f"(f))
#define UNPACK2(lo, hi, s) asm("mov.b64 {%0, %1}, %2;" : "=f"(lo), "=f"(hi) : "l"(s))

// ---------------------------------------------------------------------------
// index dtype detection: int64 little-endian => every odd 32-bit word is 0
// ---------------------------------------------------------------------------
__global__ void detect_kernel(const unsigned int* __restrict__ raw) {
    __shared__ int any;
    if (threadIdx.x == 0) any = 0;
    __syncthreads();
    int f = 0;
    for (int i = threadIdx.x; i < 2048; i += blockDim.x)
        if (raw[2 * i + 1] != 0u) f = 1;
    if (f) atomicExch(&any, 1);
    __syncthreads();
    if (threadIdx.x == 0) g_idx64 = (any == 0) ? 1 : 0;
}

__global__ void zero_agg_kernel() {
    int i = blockIdx.x * blockDim.x + threadIdx.x;   // exactly NN*D_OUT/4 threads
    ((float4*)g_agg)[i] = make_float4(0.f, 0.f, 0.f, 0.f);
}

// ---------------------------------------------------------------------------
// Edge kernel: per block of 64 edges
//   x = [nf[src] | nf[dst] | ef]  (192)  -> H = relu(x @ [We1|Wa1] + b) (256)
//   e_pre = H_e @ We2, a_pre = H_a @ Wa2 ; msg = sigmoid(a)*(e)
//   write updated_ef, atomic-scatter msg into g_agg[dst]
// SMEM: sXT[192][68] (x transposed, padded), sW1[16][256] chunk, sH[64][256],
//       sW2[128][128] reuses the sXT+sW1 region after phase 1.
// ---------------------------------------------------------------------------
#define XS 68
#define EDGE_SMEM ((192*XS + 16*256 + 64*256) * 4 + 2 * BE * 4)

__global__ __launch_bounds__(256, 1) void edge_kernel(
    const float* __restrict__ nf, const float* __restrict__ ef,
    const int* __restrict__ rawsrc, const int* __restrict__ rawdst,
    const float* __restrict__ We1, const float* __restrict__ be1,
    const float* __restrict__ We2, const float* __restrict__ be2,
    const float* __restrict__ Wa1, const float* __restrict__ ba1,
    const float* __restrict__ Wa2, const float* __restrict__ ba2,
    float* __restrict__ ef_out)
{
    extern __shared__ float sm[];
    float* sXT = sm;                          // [192][XS]
    float* sW1 = sm + 192 * XS;               // [16][256]
    float* sH  = sm + 192 * XS + 16 * 256;    // [64][256]
    int*   sSrc = (int*)(sH + 64 * 256);
    int*   sDst = sSrc + BE;

    const int tid = threadIdx.x;
    const int tx = tid & 15;
    const int ty = tid >> 4;
    const int e0 = blockIdx.x * BE;
    const int is64 = g_idx64;

    if (tid < BE) {
        int e = e0 + tid;
        sSrc[tid] = is64 ? rawsrc[2 * e] : rawsrc[e];
    } else if (tid < 2 * BE) {
        int m = tid - BE;
        int e = e0 + m;
        sDst[m] = is64 ? rawdst[2 * e] : rawdst[e];
    }
    __syncthreads();

    // gather x into transposed smem
    {
        const int w = tid >> 5, lane = tid & 31;
        #pragma unroll
        for (int r = 0; r < 8; r++) {
            int m = w * 8 + r;
            int s = sSrc[m];
            int d = sDst[m];
            const float* ns = nf + (size_t)s * D_N;
            const float* nd = nf + (size_t)d * D_N;
            const float* ee = ef + (size_t)(e0 + m) * D_N;
            sXT[lane * XS + m]          = ns[lane];
            sXT[(lane + 32) * XS + m]   = ns[lane + 32];
            sXT[(lane + 64) * XS + m]   = nd[lane];
            sXT[(lane + 96) * XS + m]   = nd[lane + 32];
            sXT[(lane + 128) * XS + m]  = ee[lane];
            sXT[(lane + 160) * XS + m]  = ee[lane + 32];
        }
    }

    // ---- phase 1: [64,192] @ [192,256], thread tile: 4 rows x 16 cols ----
    ull acc[4][8];
    #pragma unroll
    for (int i = 0; i < 4; i++)
        #pragma unroll
        for (int j = 0; j < 8; j++) acc[i][j] = 0ull;

    for (int c = 0; c < 12; c++) {
        const int k0 = c * 16;
        __syncthreads();   // prior-chunk reads of sW1 done (and gather, on c==0)
        #pragma unroll
        for (int i = 0; i < 4; i++) {
            int fidx = tid + 256 * i;   // 1024 float4s
            int kc = fidx >> 6;
            int col = (fidx & 63) * 4;
            const float* src = (col < 128) ? (We1 + (k0 + kc) * 128 + col)
                                           : (Wa1 + (k0 + kc) * 128 + (col - 128));
            *(float4*)(sW1 + kc * 256 + col) = *(const float4*)src;
        }
        __syncthreads();
        #pragma unroll
        for (int kc = 0; kc < 16; kc++) {
            float4 xv = *(const float4*)(sXT + (k0 + kc) * XS + ty * 4);
            ull xp0, xp1, xp2, xp3;
            PACK2(xp0, xv.x); PACK2(xp1, xv.y); PACK2(xp2, xv.z); PACK2(xp3, xv.w);
            #pragma unroll
            for (int j = 0; j < 4; j++) {
                ulonglong2 wv = *(const ulonglong2*)(sW1 + kc * 256 + tx * 4 + 64 * j);
                FMA2(acc[0][2*j], xp0, wv.x); FMA2(acc[0][2*j+1], xp0, wv.y);
                FMA2(acc[1][2*j], xp1, wv.x); FMA2(acc[1][2*j+1], xp1, wv.y);
                FMA2(acc[2][2*j], xp2, wv.x); FMA2(acc[2][2*j+1], xp2, wv.y);
                FMA2(acc[3][2*j], xp3, wv.x); FMA2(acc[3][2*j+1], xp3, wv.y);
            }
        }
    }

    // bias + relu -> sH[m][n]
    #pragma unroll
    for (int j = 0; j < 4; j++) {
        int n0 = tx * 4 + 64 * j;
        const float* bsrc = (n0 < 128) ? (be1 + n0) : (ba1 + n0 - 128);
        float4 bb = *(const float4*)bsrc;
        #pragma unroll
        for (int i = 0; i < 4; i++) {
            float v0, v1, v2, v3;
            UNPACK2(v0, v1, acc[i][2*j]);
            UNPACK2(v2, v3, acc[i][2*j+1]);
            v0 = fmaxf(v0 + bb.x, 0.f);
            v1 = fmaxf(v1 + bb.y, 0.f);
            v2 = fmaxf(v2 + bb.z, 0.f);
            v3 = fmaxf(v3 + bb.w, 0.f);
            *(float4*)(sH + (ty * 4 + i) * 256 + n0) = make_float4(v0, v1, v2, v3);
        }
    }
    __syncthreads();   // sXT/sW1 reads done -> safe to overwrite with W2

    // stage W2cat[128][128] = [We2 | Wa2]
    float* sW2 = sm;
    #pragma unroll
    for (int i = 0; i < 16; i++) {
        int fidx = tid + 256 * i;   // 4096 float4s
        int k = fidx >> 5;
        int c4 = fidx & 31;
        const float* src = (c4 < 16) ? (We2 + k * 64 + c4 * 4)
                                     : (Wa2 + k * 64 + (c4 - 16) * 4);
        *(float4*)(sW2 + k * 128 + c4 * 4) = *(const float4*)src;
    }
    __syncthreads();

    // ---- phase 2: e_pre = H[:,0:128]@We2 ; a_pre = H[:,128:256]@Wa2 ----
    ull ea[4][2], aa[4][2];
    #pragma unroll
    for (int i = 0; i < 4; i++) { ea[i][0] = ea[i][1] = aa[i][0] = aa[i][1] = 0ull; }

    #pragma unroll 2
    for (int k = 0; k < 128; k++) {
        ulonglong2 we = *(const ulonglong2*)(sW2 + k * 128 + tx * 4);
        ulonglong2 wa = *(const ulonglong2*)(sW2 + k * 128 + 64 + tx * 4);
        #pragma unroll
        for (int i = 0; i < 4; i++) {
            ull hp, hq;
            PACK2(hp, sH[(ty * 4 + i) * 256 + k]);
            PACK2(hq, sH[(ty * 4 + i) * 256 + 128 + k]);
            FMA2(ea[i][0], hp, we.x); FMA2(ea[i][1], hp, we.y);
            FMA2(aa[i][0], hq, wa.x); FMA2(aa[i][1], hq, wa.y);
        }
    }

    // epilogue: gate * e_out, write updated_ef, scatter into g_agg[dst]
    const int n0 = tx * 4;
    float4 bbe = *(const float4*)(be2 + n0);
    float4 bba = *(const float4*)(ba2 + n0);
    #pragma unroll
    for (int i = 0; i < 4; i++) {
        int m = ty * 4 + i;
        int e = e0 + m;
        int d = sDst[m];
        float ev0, ev1, ev2, ev3, av0, av1, av2, av3;
        UNPACK2(ev0, ev1, ea[i][0]); UNPACK2(ev2, ev3, ea[i][1]);
        UNPACK2(av0, av1, aa[i][0]); UNPACK2(av2, av3, aa[i][1]);
        ev0 += bbe.x; ev1 += bbe.y; ev2 += bbe.z; ev3 += bbe.w;
        av0 += bba.x; av1 += bba.y; av2 += bba.z; av3 += bba.w;
        float m0 = ev0 / (1.f + expf(-av0));
        float m1 = ev1 / (1.f + expf(-av1));
        float m2 = ev2 / (1.f + expf(-av2));
        float m3 = ev3 / (1.f + expf(-av3));
        *(float4*)(ef_out + (size_t)e * D_OUT + n0) = make_float4(m0, m1, m2, m3);
        float* ap = g_agg + (size_t)d * D_OUT + n0;
        atomicAdd(ap + 0, m0);
        atomicAdd(ap + 1, m1);
        atomicAdd(ap + 2, m2);
        atomicAdd(ap + 3, m3);
    }
}

// ---------------------------------------------------------------------------
// Node kernel: x = [agg | nf] (128) -> relu(x@Wn1+bn1) @ Wn2 + bn2
// SMEM: sXT[128][68], sW1[128][128], sH[64][128]; sW2[128][64] reuses sXT.
// ---------------------------------------------------------------------------
#define NODE_SMEM ((128*XS + 128*128 + 64*128) * 4)

__global__ __launch_bounds__(256, 1) void node_kernel(
    const float* __restrict__ nf,
    const float* __restrict__ Wn1, const float* __restrict__ bn1,
    const float* __restrict__ Wn2, const float* __restrict__ bn2,
    float* __restrict__ nf_out)
{
    extern __shared__ float sm[];
    float* sXT = sm;                    // [128][XS]
    float* sW1 = sm + 128 * XS;         // [128][128]
    float* sH  = sW1 + 128 * 128;       // [64][128]

    const int tid = threadIdx.x;
    const int tx = tid & 15;
    const int ty = tid >> 4;
    const int m0 = blockIdx.x * 64;
    const int w = tid >> 5, lane = tid & 31;

    #pragma unroll
    for (int r = 0; r < 8; r++) {
        int m = w * 8 + r;
        int node = m0 + m;
        float a0 = 0.f, a1 = 0.f, f0 = 0.f, f1 = 0.f;
        if (node < NN) {
            const float* ag = g_agg + (size_t)node * D_OUT;
            const float* nn = nf + (size_t)node * D_N;
            a0 = ag[lane]; a1 = ag[lane + 32];
            f0 = nn[lane]; f1 = nn[lane + 32];
        }
        sXT[lane * XS + m]        = a0;
        sXT[(lane + 32) * XS + m] = a1;
        sXT[(lane + 64) * XS + m] = f0;
        sXT[(lane + 96) * XS + m] = f1;
    }
    #pragma unroll
    for (int i = 0; i < 16; i++) {
        int fidx = tid + 256 * i;   // 4096 float4s
        int k = fidx >> 5, c4 = fidx & 31;
        *(float4*)(sW1 + k * 128 + c4 * 4) = *(const float4*)(Wn1 + k * 128 + c4 * 4);
    }
    __syncthreads();

    // phase 1: [64,128] @ [128,128]
    ull acc[4][4];
    #pragma unroll
    for (int i = 0; i < 4; i++) { acc[i][0] = acc[i][1] = acc[i][2] = acc[i][3] = 0ull; }

    #pragma unroll 4
    for (int k = 0; k < 128; k++) {
        float4 xv = *(const float4*)(sXT + k * XS + ty * 4);
        ull xp0, xp1, xp2, xp3;
        PACK2(xp0, xv.x); PACK2(xp1, xv.y); PACK2(xp2, xv.z); PACK2(xp3, xv.w);
        #pragma unroll
        for (int j = 0; j < 2; j++) {
            ulonglong2 wv = *(const ulonglong2*)(sW1 + k * 128 + tx * 4 + 64 * j);
            FMA2(acc[0][2*j], xp0, wv.x); FMA2(acc[0][2*j+1], xp0, wv.y);
            FMA2(acc[1][2*j], xp1, wv.x); FMA2(acc[1][2*j+1], xp1, wv.y);
            FMA2(acc[2][2*j], xp2, wv.x); FMA2(acc[2][2*j+1], xp2, wv.y);
            FMA2(acc[3][2*j], xp3, wv.x); FMA2(acc[3][2*j+1], xp3, wv.y);
        }
    }
    #pragma unroll
    for (int j = 0; j < 2; j++) {
        int n0 = tx * 4 + 64 * j;
        float4 bb = *(const float4*)(bn1 + n0);
        #pragma unroll
        for (int i = 0; i < 4; i++) {
            float v0, v1, v2, v3;
            UNPACK2(v0, v1, acc[i][2*j]);
            UNPACK2(v2, v3, acc[i][2*j+1]);
            v0 = fmaxf(v0 + bb.x, 0.f);
            v1 = fmaxf(v1 + bb.y, 0.f);
            v2 = fmaxf(v2 + bb.z, 0.f);
            v3 = fmaxf(v3 + bb.w, 0.f);
            *(float4*)(sH + (ty * 4 + i) * 128 + n0) = make_float4(v0, v1, v2, v3);
        }
    }
    __syncthreads();   // sXT reads done

    float* sW2 = sm;   // [128][64]
    #pragma unroll
    for (int i = 0; i < 8; i++) {
        int fidx = tid + 256 * i;   // 2048 float4s
        int k = fidx >> 4, c4 = fidx & 15;
        *(float4*)(sW2 + k * 64 + c4 * 4) = *(const float4*)(Wn2 + k * 64 + c4 * 4);
    }
    __syncthreads();

    // phase 2: [64,128] @ [128,64]
    ull oa[4][2];
    #pragma unroll
    for (int i = 0; i < 4; i++) { oa[i][0] = oa[i][1] = 0ull; }

    #pragma unroll 4
    for (int k = 0; k < 128; k++) {
        ulonglong2 wv = *(const ulonglong2*)(sW2 + k * 64 + tx * 4);
        #pragma unroll
        for (int i = 0; i < 4; i++) {
            ull hp;
            PACK2(hp, sH[(ty * 4 + i) * 128 + k]);
            FMA2(oa[i][0], hp, wv.x); FMA2(oa[i][1], hp, wv.y);
        }
    }
    const int n0 = tx * 4;
    float4 bb = *(const float4*)(bn2 + n0);
    #pragma unroll
    for (int i = 0; i < 4; i++) {
        int node = m0 + ty * 4 + i;
        if (node < NN) {
            float v0, v1, v2, v3;
            UNPACK2(v0, v1, oa[i][0]);
            UNPACK2(v2, v3, oa[i][1]);
            *(float4*)(nf_out + (size_t)node * D_OUT + n0) =
                make_float4(v0 + bb.x, v1 + bb.y, v2 + bb.z, v3 + bb.w);
        }
    }
}

// ---------------------------------------------------------------------------
extern "C" void kernel_launch(void* const* d_in, const int* in_sizes, int n_in,
                              void* d_out, int out_size)
{
    const float* nf  = (const float*)d_in[0];
    const float* ef  = (const float*)d_in[1];
    const int*   src = (const int*)d_in[2];
    const int*   dst = (const int*)d_in[3];
    const float* We1 = (const float*)d_in[4];
    const float* be1 = (const float*)d_in[5];
    const float* We2 = (const float*)d_in[6];
    const float* be2 = (const float*)d_in[7];
    const float* Wa1 = (const float*)d_in[8];
    const float* ba1 = (const float*)d_in[9];
    const float* Wa2 = (const float*)d_in[10];
    const float* ba2 = (const float*)d_in[11];
    const float* Wn1 = (const float*)d_in[12];
    const float* bn1 = (const float*)d_in[13];
    const float* Wn2 = (const float*)d_in[14];
    const float* bn2 = (const float*)d_in[15];

    float* nf_out = (float*)d_out;
    float* ef_out = nf_out + (size_t)NN * D_OUT;

    cudaFuncSetAttribute(edge_kernel, cudaFuncAttributeMaxDynamicSharedMemorySize, EDGE_SMEM);
    cudaFuncSetAttribute(node_kernel, cudaFuncAttributeMaxDynamicSharedMemorySize, NODE_SMEM);

    detect_kernel<<<1, 256>>>((const unsigned int*)d_in[2]);
    zero_agg_kernel<<<(NN * D_OUT / 4) / 256, 256>>>();
    edge_kernel<<<E_EDGES / BE, 256, EDGE_SMEM>>>(
        nf, ef, src, dst, We1, be1, We2, be2, Wa1, ba1, Wa2, ba2, ef_out);
    node_kernel<<<(NN + 63) / 64, 256, NODE_SMEM>>>(nf, Wn1, bn1, Wn2, bn2, nf_out);
}